// round 15
// baseline (speedup 1.0000x reference)
#include <cuda_runtime.h>

#define BB 32
#define TT 512
#define DD 384
#define ML 4096
#define D4 (DD / 4)        // 96 float4 per row
#define NTOKBLK (BB * TT / 4)   // 4096 token blocks (4 tokens each)
#define NZROWS  8
#define NZBLK   (BB * (ML / NZROWS))  // 16384 frame blocks

// Block-wide sum of per-thread 'v' over 96 threads (3 warps). All threads
// get the result.
__device__ __forceinline__ int block_sum96(int v, int* s3) {
    #pragma unroll
    for (int off = 16; off > 0; off >>= 1)
        v += __shfl_down_sync(0xffffffffu, v, off);
    const int w = threadIdx.x >> 5;
    if ((threadIdx.x & 31) == 0) s3[w] = v;
    __syncthreads();
    return s3[0] + s3[1] + s3[2];
}

// Single fused kernel. 96 threads per block (threadIdx.x == c4).
// Block types INTERLEAVED 1:4 (every 5th block is a token block) so the
// DRAM read stream (x gathers) stays co-resident with the store-only
// zero-fill work across the whole kernel instead of phasing.
//  token blocks: 4 tokens; address-static x loads issued first (MLP=4),
//    per-batch prefix recomputed in-block (hidden under x-load latency).
//    Each row stored dur times to consecutive frames.
//  frame blocks: 8-frame chunk; total = full-batch reduce; mel_pos from
//    threads 0..1; zero-fill rows with f >= total.
__global__ __launch_bounds__(96) void lr_fused(const float4* __restrict__ x,
                                               const int*    __restrict__ dur,
                                               float4* __restrict__ out,
                                               float4* __restrict__ mel4) {
    __shared__ int s3[3];
    const int c4 = threadIdx.x;
    const int grp = blockIdx.x / 5;
    const int rem = blockIdx.x - grp * 5;

    if (rem == 0) {
        const int tb = grp;                 // 0..4095
        const int b  = tb >> 7;             // TT/4 = 128 token-groups/batch
        const int t0 = (tb & 127) << 2;

        // Streaming x loads: addresses depend only on blockIdx -> issue now.
        const float4* xr = x + ((size_t)b * TT + t0) * D4 + c4;
        const float4 v0 = __ldg(xr);
        const float4 v1 = __ldg(xr + D4);
        const float4 v2 = __ldg(xr + 2 * D4);
        const float4 v3 = __ldg(xr + 3 * D4);

        // Prefix over dur[b][0..t0) (overlapped with x loads).
        const int4* dq = reinterpret_cast<const int4*>(dur + b * TT);
        const int nq = t0 >> 2;             // int4s before this group
        int part = 0;
        for (int q = c4; q < nq; q += 96) {
            const int4 u = __ldg(&dq[q]);
            part += u.x + u.y + u.z + u.w;
        }
        const int4 dv = __ldg(&dq[nq]);     // d0..d3
        const int prefix = block_sum96(part, s3);

        const int s0 = prefix;
        const int s1 = s0 + dv.x;
        const int s2 = s1 + dv.y;
        const int s3s = s2 + dv.z;

        float4* ob = out + (size_t)b * ML * D4 + c4;
        {
            float4* o = ob + (size_t)s0 * D4;
            for (int j = 0; j < dv.x; ++j) __stcs(o + (size_t)j * D4, v0);
        }
        {
            float4* o = ob + (size_t)s1 * D4;
            for (int j = 0; j < dv.y; ++j) __stcs(o + (size_t)j * D4, v1);
        }
        {
            float4* o = ob + (size_t)s2 * D4;
            for (int j = 0; j < dv.z; ++j) __stcs(o + (size_t)j * D4, v2);
        }
        {
            float4* o = ob + (size_t)s3s * D4;
            for (int j = 0; j < dv.w; ++j) __stcs(o + (size_t)j * D4, v3);
        }
    } else {
        const int zb = grp * 4 + (rem - 1); // 0..16383
        const int b  = zb >> 9;             // ML/8 = 512 chunks per batch
        const int f0 = (zb & 511) << 3;

        // total = sum of all 512 durations (128 int4s; L1/L2 hits).
        const int4* dq = reinterpret_cast<const int4*>(dur + b * TT);
        int part = 0;
        {
            const int4 u = __ldg(&dq[c4]);
            part = u.x + u.y + u.z + u.w;
            if (c4 < 32) {
                const int4 u2 = __ldg(&dq[c4 + 96]);
                part += u2.x + u2.y + u2.z + u2.w;
            }
        }
        const int total = block_sum96(part, s3);

        // mel_pos for these 8 frames: threads 0..1 each write a float4.
        if (c4 < 2) {
            const int f = f0 + c4 * 4;
            float4 m;
            m.x = (f     < total) ? (float)(f + 1) : 0.0f;
            m.y = (f + 1 < total) ? (float)(f + 2) : 0.0f;
            m.z = (f + 2 < total) ? (float)(f + 3) : 0.0f;
            m.w = (f + 3 < total) ? (float)(f + 4) : 0.0f;
            mel4[(b * ML + f) >> 2] = m;
        }

        if (f0 + NZROWS <= total) return;   // fully valid: scatter covers it

        const float4 z = make_float4(0.0f, 0.0f, 0.0f, 0.0f);
        float4* o = out + ((size_t)b * ML + f0) * D4 + c4;
        const int jlo = (total > f0) ? (total - f0) : 0;
        #pragma unroll
        for (int j = 0; j < NZROWS; ++j) {
            if (j >= jlo) __stcs(o + (size_t)j * D4, z);
        }
    }
}

extern "C" void kernel_launch(void* const* d_in, const int* in_sizes, int n_in,
                              void* d_out, int out_size) {
    const float* x   = (const float*)d_in[0];
    const int*   dur = (const int*)d_in[1];

    float* out = (float*)d_out;                 // [B, ML, D] f32
    float* mel = out + (size_t)BB * ML * DD;    // [B, ML] written as float

    lr_fused<<<NTOKBLK + NZBLK, 96>>>((const float4*)x, dur,
                                      (float4*)out, (float4*)mel);
}

// round 16
// speedup vs baseline: 1.0490x; 1.0490x over previous
#include <cuda_runtime.h>

#define BB 32
#define TT 512
#define DD 384
#define ML 4096
#define D4 (DD / 4)        // 96 float4 per row
#define NTOKBLK (BB * TT / 4)   // 4096 token blocks (4 tokens each)
#define NZROWS  8
#define NZBLK   (BB * (ML / NZROWS))  // 16384 frame blocks

// Block-wide sum of per-thread 'v' over 96 threads (3 warps). All threads
// get the result.
__device__ __forceinline__ int block_sum96(int v, int* s3) {
    #pragma unroll
    for (int off = 16; off > 0; off >>= 1)
        v += __shfl_down_sync(0xffffffffu, v, off);
    const int w = threadIdx.x >> 5;
    if ((threadIdx.x & 31) == 0) s3[w] = v;
    __syncthreads();
    return s3[0] + s3[1] + s3[2];
}

// Single fused kernel. 96 threads per block (threadIdx.x == c4).
// Blocks in natural (phased) order: consecutive blocks write consecutive
// output regions -> long same-page DRAM write bursts.
//  blocks [0, NTOKBLK): 4 tokens; address-static x loads issued first
//    (MLP=4), per-batch prefix recomputed in-block (L1/L2 hits, hidden
//    under x-load latency). Each row stored dur times to consecutive
//    frames with streaming stores.
//  blocks [NTOKBLK, +NZBLK): 8-frame chunk; total = full-batch reduce;
//    mel_pos from threads 0..1; zero-fill rows with f >= total.
__global__ __launch_bounds__(96) void lr_fused(const float4* __restrict__ x,
                                               const int*    __restrict__ dur,
                                               float4* __restrict__ out,
                                               float4* __restrict__ mel4) {
    __shared__ int s3[3];
    const int c4 = threadIdx.x;

    if (blockIdx.x < NTOKBLK) {
        const int tb = blockIdx.x;
        const int b  = tb >> 7;             // TT/4 = 128 token-groups/batch
        const int t0 = (tb & 127) << 2;

        // Streaming x loads: addresses depend only on blockIdx -> issue now.
        const float4* xr = x + ((size_t)b * TT + t0) * D4 + c4;
        const float4 v0 = __ldg(xr);
        const float4 v1 = __ldg(xr + D4);
        const float4 v2 = __ldg(xr + 2 * D4);
        const float4 v3 = __ldg(xr + 3 * D4);

        // Prefix over dur[b][0..t0) (overlapped with x loads).
        const int4* dq = reinterpret_cast<const int4*>(dur + b * TT);
        const int nq = t0 >> 2;             // int4s before this group
        int part = 0;
        for (int q = c4; q < nq; q += 96) {
            const int4 u = __ldg(&dq[q]);
            part += u.x + u.y + u.z + u.w;
        }
        const int4 dv = __ldg(&dq[nq]);     // d0..d3
        const int prefix = block_sum96(part, s3);

        const int s0 = prefix;
        const int s1 = s0 + dv.x;
        const int s2 = s1 + dv.y;
        const int s3s = s2 + dv.z;

        float4* ob = out + (size_t)b * ML * D4 + c4;
        {
            float4* o = ob + (size_t)s0 * D4;
            for (int j = 0; j < dv.x; ++j) __stcs(o + (size_t)j * D4, v0);
        }
        {
            float4* o = ob + (size_t)s1 * D4;
            for (int j = 0; j < dv.y; ++j) __stcs(o + (size_t)j * D4, v1);
        }
        {
            float4* o = ob + (size_t)s2 * D4;
            for (int j = 0; j < dv.z; ++j) __stcs(o + (size_t)j * D4, v2);
        }
        {
            float4* o = ob + (size_t)s3s * D4;
            for (int j = 0; j < dv.w; ++j) __stcs(o + (size_t)j * D4, v3);
        }
    } else {
        const int zb = blockIdx.x - NTOKBLK;
        const int b  = zb >> 9;             // ML/8 = 512 chunks per batch
        const int f0 = (zb & 511) << 3;

        // total = sum of all 512 durations (128 int4s; L1/L2 hits).
        const int4* dq = reinterpret_cast<const int4*>(dur + b * TT);
        int part = 0;
        {
            const int4 u = __ldg(&dq[c4]);
            part = u.x + u.y + u.z + u.w;
            if (c4 < 32) {
                const int4 u2 = __ldg(&dq[c4 + 96]);
                part += u2.x + u2.y + u2.z + u2.w;
            }
        }
        const int total = block_sum96(part, s3);

        // mel_pos for these 8 frames: threads 0..1 each write a float4.
        if (c4 < 2) {
            const int f = f0 + c4 * 4;
            float4 m;
            m.x = (f     < total) ? (float)(f + 1) : 0.0f;
            m.y = (f + 1 < total) ? (float)(f + 2) : 0.0f;
            m.z = (f + 2 < total) ? (float)(f + 3) : 0.0f;
            m.w = (f + 3 < total) ? (float)(f + 4) : 0.0f;
            mel4[(b * ML + f) >> 2] = m;
        }

        if (f0 + NZROWS <= total) return;   // fully valid: scatter covers it

        const float4 z = make_float4(0.0f, 0.0f, 0.0f, 0.0f);
        float4* o = out + ((size_t)b * ML + f0) * D4 + c4;
        const int jlo = (total > f0) ? (total - f0) : 0;
        #pragma unroll
        for (int j = 0; j < NZROWS; ++j) {
            if (j >= jlo) __stcs(o + (size_t)j * D4, z);
        }
    }
}

extern "C" void kernel_launch(void* const* d_in, const int* in_sizes, int n_in,
                              void* d_out, int out_size) {
    const float* x   = (const float*)d_in[0];
    const int*   dur = (const int*)d_in[1];

    float* out = (float*)d_out;                 // [B, ML, D] f32
    float* mel = out + (size_t)BB * ML * DD;    // [B, ML] written as float

    lr_fused<<<NTOKBLK + NZBLK, 96>>>((const float4*)x, dur,
                                      (float4*)out, (float4*)mel);
}

// round 17
// speedup vs baseline: 1.0500x; 1.0010x over previous
#include <cuda_runtime.h>

#define BB 32
#define TT 512
#define DD 384
#define ML 4096
#define D4 (DD / 4)        // 96 float4 per row
#define NTOKBLK (BB * TT / 4)   // 4096 token blocks (4 tokens each)
#define NZROWS  8
#define NZBLK   (BB * (ML / NZROWS))  // 16384 frame blocks

// Block-wide sum of per-thread 'v' over 96 threads (3 warps). All threads
// get the result.
__device__ __forceinline__ int block_sum96(int v, int* s3) {
    #pragma unroll
    for (int off = 16; off > 0; off >>= 1)
        v += __shfl_down_sync(0xffffffffu, v, off);
    const int w = threadIdx.x >> 5;
    if ((threadIdx.x & 31) == 0) s3[w] = v;
    __syncthreads();
    return s3[0] + s3[1] + s3[2];
}

// Single fused kernel. 96 threads per block (threadIdx.x == c4).
// Blocks in natural (phased) order: consecutive blocks write consecutive
// output regions -> long same-page DRAM write bursts.
//  blocks [0, NTOKBLK): 4 tokens; address-static x loads issued first
//    (MLP=4), per-batch prefix recomputed in-block (L1/L2 hits, hidden
//    under x-load latency). Each row stored dur times to consecutive
//    frames with streaming stores.
//  blocks [NTOKBLK, +NZBLK): 8-frame chunk; total = full-batch reduce;
//    mel_pos from threads 0..1; zero-fill rows with f >= total.
__global__ __launch_bounds__(96) void lr_fused(const float4* __restrict__ x,
                                               const int*    __restrict__ dur,
                                               float4* __restrict__ out,
                                               float4* __restrict__ mel4) {
    __shared__ int s3[3];
    const int c4 = threadIdx.x;

    if (blockIdx.x < NTOKBLK) {
        const int tb = blockIdx.x;
        const int b  = tb >> 7;             // TT/4 = 128 token-groups/batch
        const int t0 = (tb & 127) << 2;

        // Streaming x loads: addresses depend only on blockIdx -> issue now.
        const float4* xr = x + ((size_t)b * TT + t0) * D4 + c4;
        const float4 v0 = __ldg(xr);
        const float4 v1 = __ldg(xr + D4);
        const float4 v2 = __ldg(xr + 2 * D4);
        const float4 v3 = __ldg(xr + 3 * D4);

        // Prefix over dur[b][0..t0) (overlapped with x loads).
        const int4* dq = reinterpret_cast<const int4*>(dur + b * TT);
        const int nq = t0 >> 2;             // int4s before this group
        int part = 0;
        for (int q = c4; q < nq; q += 96) {
            const int4 u = __ldg(&dq[q]);
            part += u.x + u.y + u.z + u.w;
        }
        const int4 dv = __ldg(&dq[nq]);     // d0..d3
        const int prefix = block_sum96(part, s3);

        const int s0 = prefix;
        const int s1 = s0 + dv.x;
        const int s2 = s1 + dv.y;
        const int s3s = s2 + dv.z;

        float4* ob = out + (size_t)b * ML * D4 + c4;
        {
            float4* o = ob + (size_t)s0 * D4;
            for (int j = 0; j < dv.x; ++j) __stcs(o + (size_t)j * D4, v0);
        }
        {
            float4* o = ob + (size_t)s1 * D4;
            for (int j = 0; j < dv.y; ++j) __stcs(o + (size_t)j * D4, v1);
        }
        {
            float4* o = ob + (size_t)s2 * D4;
            for (int j = 0; j < dv.z; ++j) __stcs(o + (size_t)j * D4, v2);
        }
        {
            float4* o = ob + (size_t)s3s * D4;
            for (int j = 0; j < dv.w; ++j) __stcs(o + (size_t)j * D4, v3);
        }
    } else {
        const int zb = blockIdx.x - NTOKBLK;
        const int b  = zb >> 9;             // ML/8 = 512 chunks per batch
        const int f0 = (zb & 511) << 3;

        // total = sum of all 512 durations (128 int4s; L1/L2 hits).
        const int4* dq = reinterpret_cast<const int4*>(dur + b * TT);
        int part = 0;
        {
            const int4 u = __ldg(&dq[c4]);
            part = u.x + u.y + u.z + u.w;
            if (c4 < 32) {
                const int4 u2 = __ldg(&dq[c4 + 96]);
                part += u2.x + u2.y + u2.z + u2.w;
            }
        }
        const int total = block_sum96(part, s3);

        // mel_pos for these 8 frames: threads 0..1 each write a float4.
        if (c4 < 2) {
            const int f = f0 + c4 * 4;
            float4 m;
            m.x = (f     < total) ? (float)(f + 1) : 0.0f;
            m.y = (f + 1 < total) ? (float)(f + 2) : 0.0f;
            m.z = (f + 2 < total) ? (float)(f + 3) : 0.0f;
            m.w = (f + 3 < total) ? (float)(f + 4) : 0.0f;
            mel4[(b * ML + f) >> 2] = m;
        }

        if (f0 + NZROWS <= total) return;   // fully valid: scatter covers it

        const float4 z = make_float4(0.0f, 0.0f, 0.0f, 0.0f);
        float4* o = out + ((size_t)b * ML + f0) * D4 + c4;
        const int jlo = (total > f0) ? (total - f0) : 0;
        #pragma unroll
        for (int j = 0; j < NZROWS; ++j) {
            if (j >= jlo) __stcs(o + (size_t)j * D4, z);
        }
    }
}

extern "C" void kernel_launch(void* const* d_in, const int* in_sizes, int n_in,
                              void* d_out, int out_size) {
    const float* x   = (const float*)d_in[0];
    const int*   dur = (const int*)d_in[1];

    float* out = (float*)d_out;                 // [B, ML, D] f32
    float* mel = out + (size_t)BB * ML * DD;    // [B, ML] written as float

    lr_fused<<<NTOKBLK + NZBLK, 96>>>((const float4*)x, dur,
                                      (float4*)out, (float4*)mel);
}